// round 11
// baseline (speedup 1.0000x reference)
#include <cuda_runtime.h>
#include <cuda_bf16.h>

// BackwardRPM: 16384 independent 200-step projected-gradient solves.
// grad6 = M h + c, M = R6^T R W2^T (6x64), c = R6^T R (b2 - spec).
// R9->R10: 8 threads/element (contiguous 4-pair slices, LDS.128 weight loads),
// 512 thr/block x 256 blocks, __launch_bounds__(512,2) -> 2 blocks/SM,
// tanh via MUFU.TANH (tanh.approx.f32).

#define STEPS 200
#define LRATE 0.01f
#define BATCH 16384
#define HID   64
#define HID2  32
#define PROJ  8
#define NSPEC 40
#define NU    6

typedef unsigned long long u64;

#define PK(d, lo, hi)  asm("mov.b64 %0, {%1, %2};" : "=l"(d) : "f"(lo), "f"(hi))
#define UPK(lo, hi, s) asm("mov.b64 {%0, %1}, %2;" : "=f"(lo), "=f"(hi) : "l"(s))
#define FMA2(d, a, b, c) \
    asm("fma.rn.f32x2 %0, %1, %2, %3;" : "=l"(d) : "l"(a), "l"(b), "l"(c))
#define MUL2(d, a, b) \
    asm("mul.rn.f32x2 %0, %1, %2;" : "=l"(d) : "l"(a), "l"(b))

__device__ __forceinline__ float tanh_hw(float x) {
    float r;
    asm("tanh.approx.f32 %0, %1;" : "=f"(r) : "f"(x));
    return r;
}

__global__ void __launch_bounds__(512, 2)
backward_rpm_kernel(const float* __restrict__ spectrum,  // (16384, 40)
                    const float* __restrict__ W1,        // (6, 64)
                    const float* __restrict__ b1,        // (64,)
                    const float* __restrict__ W2,        // (64, 40)
                    const float* __restrict__ b2,        // (40,)
                    const float* __restrict__ R,         // (8, 40)
                    float* __restrict__ out)             // (16384, 6)
{
    __shared__ float sA [PROJ * HID];       // scratch: A = R W2^T
    __shared__ u64   sW1p[NU * HID2];       // W1 packed pairs
    __shared__ u64   sB1p[HID2];
    __shared__ u64   sMp [NU * HID2];       // M = R6^T A, packed pairs
    __shared__ float sP  [NU * NSPEC];      // P = R6^T R
    __shared__ float sB2 [NSPEC];

    const int tid = threadIdx.x;

    // ---- one-time weight prep ----
    {
        float* fW1 = (float*)sW1p;
        for (int i = tid; i < NU * HID; i += 512) fW1[i] = W1[i];
        if (tid < HID)   ((float*)sB1p)[tid] = b1[tid];
        if (tid < NSPEC) sB2[tid] = b2[tid];

        // A[p][j] = sum_k R[p][k] * W2[j][k]  (512 entries, one per thread)
        {
            int p = tid >> 6, j = tid & 63;
            float acc = 0.0f;
            #pragma unroll
            for (int k = 0; k < NSPEC; k++)
                acc = fmaf(R[p * NSPEC + k], W2[j * NSPEC + k], acc);
            sA[tid] = acc;
        }
        __syncthreads();

        // M[i][j] = sum_p R[p][i] * A[p][j]  (384 entries)
        float* fM = (float*)sMp;
        for (int idx = tid; idx < NU * HID; idx += 512) {
            int i = idx >> 6, j = idx & 63;
            float acc = 0.0f;
            #pragma unroll
            for (int p = 0; p < PROJ; p++)
                acc = fmaf(R[p * NSPEC + i], sA[p * HID + j], acc);
            fM[idx] = acc;
        }
        // P[i][k] = sum_p R[p][i] * R[p][k]  (240 entries)
        for (int idx = tid; idx < NU * NSPEC; idx += 512) {
            int i = idx / NSPEC, k = idx % NSPEC;
            float acc = 0.0f;
            #pragma unroll
            for (int p = 0; p < PROJ; p++)
                acc = fmaf(R[p * NSPEC + i], R[p * NSPEC + k], acc);
            sP[idx] = acc;
        }
        __syncthreads();
    }

    // ---- per-element setup: 8 threads per element, contiguous pair slices ----
    const int s    = tid & 7;                        // slice: pairs s*4 .. s*4+3
    const int elem = blockIdx.x * 64 + (tid >> 3);
    const float* sp = spectrum + elem * NSPEC;

    // cl[i] = LR * (P (b2 - spec))[i]   (duplicated across the 8 slices)
    float cl[NU];
    #pragma unroll
    for (int i = 0; i < NU; i++) {
        float acc = 0.0f;
        #pragma unroll
        for (int k = 0; k < NSPEC; k++)
            acc = fmaf(sP[i * NSPEC + k], sB2[k] - sp[k], acc);
        cl[i] = LRATE * acc;
    }

    float u[NU];
    #pragma unroll
    for (int k = 0; k < NU; k++) u[k] = 0.5f;

    const int base = s * 4;  // first pair index of this slice

    #pragma unroll 1
    for (int step = 0; step < STEPS; step++) {
        // duplicated-packed u
        u64 ud[NU];
        #pragma unroll
        for (int k = 0; k < NU; k++) PK(ud[k], u[k], u[k]);

        // ---- pre-activation for this slice's 4 pairs (LDS.128 loads) ----
        u64 pre[4];
        {
            const ulonglong2* bv = reinterpret_cast<const ulonglong2*>(&sB1p[base]);
            ulonglong2 t0 = bv[0], t1 = bv[1];
            pre[0] = t0.x; pre[1] = t0.y; pre[2] = t1.x; pre[3] = t1.y;
        }
        #pragma unroll
        for (int k = 0; k < NU; k++) {
            const ulonglong2* wv =
                reinterpret_cast<const ulonglong2*>(&sW1p[k * HID2 + base]);
            ulonglong2 w0 = wv[0], w1 = wv[1];
            FMA2(pre[0], ud[k], w0.x, pre[0]);
            FMA2(pre[1], ud[k], w0.y, pre[1]);
            FMA2(pre[2], ud[k], w1.x, pre[2]);
            FMA2(pre[3], ud[k], w1.y, pre[3]);
        }

        // ---- h = tanh(pre) via MUFU.TANH ----
        #pragma unroll
        for (int jj = 0; jj < 4; jj++) {
            float a, b;
            UPK(a, b, pre[jj]);
            a = tanh_hw(a);
            b = tanh_hw(b);
            PK(pre[jj], a, b);
        }

        // ---- grad partials: gp[i] = sum over slice pairs of M2[i][jp]*h2[jp] ----
        u64 gp[NU];
        #pragma unroll
        for (int i = 0; i < NU; i++) {
            const ulonglong2* mv =
                reinterpret_cast<const ulonglong2*>(&sMp[i * HID2 + base]);
            ulonglong2 m0 = mv[0], m1 = mv[1];
            MUL2(gp[i], m0.x, pre[0]);
            FMA2(gp[i], m0.y, pre[1], gp[i]);
            FMA2(gp[i], m1.x, pre[2], gp[i]);
            FMA2(gp[i], m1.y, pre[3], gp[i]);
        }

        // ---- horizontal + 8-lane butterfly reduce ----
        float g[NU];
        #pragma unroll
        for (int i = 0; i < NU; i++) {
            float a, b;
            UPK(a, b, gp[i]);
            g[i] = a + b;
        }
        #pragma unroll
        for (int i = 0; i < NU; i++)
            g[i] += __shfl_xor_sync(0xFFFFFFFFu, g[i], 1);
        #pragma unroll
        for (int i = 0; i < NU; i++)
            g[i] += __shfl_xor_sync(0xFFFFFFFFu, g[i], 2);
        #pragma unroll
        for (int i = 0; i < NU; i++)
            g[i] += __shfl_xor_sync(0xFFFFFFFFu, g[i], 4);

        // ---- update + clamp (all 8 lanes identical) ----
        #pragma unroll
        for (int i = 0; i < NU; i++) {
            float t = fmaf(-LRATE, g[i], u[i]) - cl[i];
            u[i] = fminf(fmaxf(t, 0.0f), 1.0f);
        }
    }

    if (s == 0) {
        #pragma unroll
        for (int k = 0; k < NU; k++)
            out[elem * NU + k] = u[k];
    }
}

extern "C" void kernel_launch(void* const* d_in, const int* in_sizes, int n_in,
                              void* d_out, int out_size) {
    const float* spectrum = (const float*)d_in[0];
    const float* W1 = (const float*)d_in[1];
    const float* b1 = (const float*)d_in[2];
    const float* W2 = (const float*)d_in[3];
    const float* b2 = (const float*)d_in[4];
    const float* R  = (const float*)d_in[5];
    float* out = (float*)d_out;

    backward_rpm_kernel<<<BATCH / 64, 512>>>(spectrum, W1, b1, W2, b2, R, out);
}

// round 15
// speedup vs baseline: 1.2713x; 1.2713x over previous
#include <cuda_runtime.h>
#include <cuda_bf16.h>

// BackwardRPM: 16384 independent 200-step projected-gradient solves.
// grad6 = M h + c, M = R6^T R W2^T (6x64), c = R6^T R (b2 - spec).
// R11: 4 threads/element with CONTIGUOUS 8-pair slices (LDS.128 weight loads),
// MUFU.TANH activation, 512 thr/block x 128 blocks, launch_bounds(512,1)
// (128 regs; R10's 8-way split + 64-reg cap was the regression).

#define STEPS 200
#define LRATE 0.01f
#define BATCH 16384
#define HID   64
#define HID2  32
#define PROJ  8
#define NSPEC 40
#define NU    6

typedef unsigned long long u64;

#define PK(d, lo, hi)  asm("mov.b64 %0, {%1, %2};" : "=l"(d) : "f"(lo), "f"(hi))
#define UPK(lo, hi, s) asm("mov.b64 {%0, %1}, %2;" : "=f"(lo), "=f"(hi) : "l"(s))
#define FMA2(d, a, b, c) \
    asm("fma.rn.f32x2 %0, %1, %2, %3;" : "=l"(d) : "l"(a), "l"(b), "l"(c))
#define MUL2(d, a, b) \
    asm("mul.rn.f32x2 %0, %1, %2;" : "=l"(d) : "l"(a), "l"(b))

__device__ __forceinline__ float tanh_hw(float x) {
    float r;
    asm("tanh.approx.f32 %0, %1;" : "=f"(r) : "f"(x));
    return r;
}

__global__ void __launch_bounds__(512, 1)
backward_rpm_kernel(const float* __restrict__ spectrum,  // (16384, 40)
                    const float* __restrict__ W1,        // (6, 64)
                    const float* __restrict__ b1,        // (64,)
                    const float* __restrict__ W2,        // (64, 40)
                    const float* __restrict__ b2,        // (40,)
                    const float* __restrict__ R,         // (8, 40)
                    float* __restrict__ out)             // (16384, 6)
{
    __shared__ float sA [PROJ * HID];       // scratch: A = R W2^T
    __shared__ u64   sW1p[NU * HID2];       // W1 packed pairs
    __shared__ u64   sB1p[HID2];
    __shared__ u64   sMp [NU * HID2];       // M = R6^T A, packed pairs
    __shared__ float sP  [NU * NSPEC];      // P = R6^T R
    __shared__ float sB2 [NSPEC];

    const int tid = threadIdx.x;

    // ---- one-time weight prep ----
    {
        float* fW1 = (float*)sW1p;
        for (int i = tid; i < NU * HID; i += 512) fW1[i] = W1[i];
        if (tid < HID)   ((float*)sB1p)[tid] = b1[tid];
        if (tid < NSPEC) sB2[tid] = b2[tid];

        // A[p][j] = sum_k R[p][k] * W2[j][k]  (512 entries, one per thread)
        {
            int p = tid >> 6, j = tid & 63;
            float acc = 0.0f;
            #pragma unroll
            for (int k = 0; k < NSPEC; k++)
                acc = fmaf(R[p * NSPEC + k], W2[j * NSPEC + k], acc);
            sA[tid] = acc;
        }
        __syncthreads();

        // M[i][j] = sum_p R[p][i] * A[p][j]  (384 entries)
        float* fM = (float*)sMp;
        for (int idx = tid; idx < NU * HID; idx += 512) {
            int i = idx >> 6, j = idx & 63;
            float acc = 0.0f;
            #pragma unroll
            for (int p = 0; p < PROJ; p++)
                acc = fmaf(R[p * NSPEC + i], sA[p * HID + j], acc);
            fM[idx] = acc;
        }
        // P[i][k] = sum_p R[p][i] * R[p][k]  (240 entries)
        for (int idx = tid; idx < NU * NSPEC; idx += 512) {
            int i = idx / NSPEC, k = idx % NSPEC;
            float acc = 0.0f;
            #pragma unroll
            for (int p = 0; p < PROJ; p++)
                acc = fmaf(R[p * NSPEC + i], R[p * NSPEC + k], acc);
            sP[idx] = acc;
        }
        __syncthreads();
    }

    // ---- per-element setup: 4 threads/element, contiguous 8-pair slices ----
    const int s    = tid & 3;                 // slice: pairs s*8 .. s*8+7
    const int elem = blockIdx.x * 128 + (tid >> 2);
    const float* sp = spectrum + elem * NSPEC;
    const int base = s * 8;                   // first pair index (u64 units)

    // cl[i] = LR * (P (b2 - spec))[i]   (duplicated across the 4 slices)
    float cl[NU];
    #pragma unroll
    for (int i = 0; i < NU; i++) {
        float acc = 0.0f;
        #pragma unroll
        for (int k = 0; k < NSPEC; k++)
            acc = fmaf(sP[i * NSPEC + k], sB2[k] - sp[k], acc);
        cl[i] = LRATE * acc;
    }

    float u[NU];
    #pragma unroll
    for (int k = 0; k < NU; k++) u[k] = 0.5f;

    #pragma unroll 1
    for (int step = 0; step < STEPS; step++) {
        // duplicated-packed u
        u64 ud[NU];
        #pragma unroll
        for (int k = 0; k < NU; k++) PK(ud[k], u[k], u[k]);

        // ---- pre-activation for this slice's 8 pairs (LDS.128 loads) ----
        u64 pre[8];
        {
            const ulonglong2* bv = reinterpret_cast<const ulonglong2*>(&sB1p[base]);
            #pragma unroll
            for (int c = 0; c < 4; c++) {
                ulonglong2 t = bv[c];
                pre[c * 2]     = t.x;
                pre[c * 2 + 1] = t.y;
            }
        }
        #pragma unroll
        for (int k = 0; k < NU; k++) {
            const ulonglong2* wv =
                reinterpret_cast<const ulonglong2*>(&sW1p[k * HID2 + base]);
            #pragma unroll
            for (int c = 0; c < 4; c++) {
                ulonglong2 w = wv[c];
                FMA2(pre[c * 2],     ud[k], w.x, pre[c * 2]);
                FMA2(pre[c * 2 + 1], ud[k], w.y, pre[c * 2 + 1]);
            }
        }

        // ---- h = tanh(pre) via MUFU.TANH ----
        #pragma unroll
        for (int jj = 0; jj < 8; jj++) {
            float a, b;
            UPK(a, b, pre[jj]);
            a = tanh_hw(a);
            b = tanh_hw(b);
            PK(pre[jj], a, b);
        }

        // ---- grad partials: gp[i] = sum over slice pairs of M2[i][jp]*h2[jp] ----
        u64 gp[NU];
        #pragma unroll
        for (int i = 0; i < NU; i++) {
            const ulonglong2* mv =
                reinterpret_cast<const ulonglong2*>(&sMp[i * HID2 + base]);
            ulonglong2 m0 = mv[0];
            MUL2(gp[i], m0.x, pre[0]);
            FMA2(gp[i], m0.y, pre[1], gp[i]);
            #pragma unroll
            for (int c = 1; c < 4; c++) {
                ulonglong2 m = mv[c];
                FMA2(gp[i], m.x, pre[c * 2],     gp[i]);
                FMA2(gp[i], m.y, pre[c * 2 + 1], gp[i]);
            }
        }

        // ---- horizontal + 4-lane butterfly reduce ----
        float g[NU];
        #pragma unroll
        for (int i = 0; i < NU; i++) {
            float a, b;
            UPK(a, b, gp[i]);
            g[i] = a + b;
        }
        #pragma unroll
        for (int i = 0; i < NU; i++)
            g[i] += __shfl_xor_sync(0xFFFFFFFFu, g[i], 1);
        #pragma unroll
        for (int i = 0; i < NU; i++)
            g[i] += __shfl_xor_sync(0xFFFFFFFFu, g[i], 2);

        // ---- update + clamp (all 4 lanes identical) ----
        #pragma unroll
        for (int i = 0; i < NU; i++) {
            float t = fmaf(-LRATE, g[i], u[i]) - cl[i];
            u[i] = fminf(fmaxf(t, 0.0f), 1.0f);
        }
    }

    if (s == 0) {
        #pragma unroll
        for (int k = 0; k < NU; k++)
            out[elem * NU + k] = u[k];
    }
}

extern "C" void kernel_launch(void* const* d_in, const int* in_sizes, int n_in,
                              void* d_out, int out_size) {
    const float* spectrum = (const float*)d_in[0];
    const float* W1 = (const float*)d_in[1];
    const float* b1 = (const float*)d_in[2];
    const float* W2 = (const float*)d_in[3];
    const float* b2 = (const float*)d_in[4];
    const float* R  = (const float*)d_in[5];
    float* out = (float*)d_out;

    backward_rpm_kernel<<<BATCH / 128, 512>>>(spectrum, W1, b1, W2, b2, R, out);
}

// round 17
// speedup vs baseline: 1.2742x; 1.0023x over previous
#include <cuda_runtime.h>
#include <cuda_bf16.h>

// BackwardRPM: 16384 independent 200-step projected-gradient solves.
// grad6 = M h + c, M = R6^T R W2^T (6x64), c = R6^T R (b2 - spec).
// R15: 4 threads/element, 8-pair slices, MUFU.TANH, LDS.128 weight loads
// with a BANK-CONFLICT-FREE swizzled layout (16B chunks interleaved by
// slice: chunk index = c*4 + s, so a warp's 4 unique 16B addresses are 64
// consecutive bytes). R11's layout had a 2-way conflict on every LDS.128.
// Also folds the constant term cl into the gp-init FMA2 (lane s==0).

#define STEPS 200
#define LRATE 0.01f
#define BATCH 16384
#define HID   64
#define HID2  32
#define PROJ  8
#define NSPEC 40
#define NU    6

typedef unsigned long long u64;

#define PK(d, lo, hi)  asm("mov.b64 %0, {%1, %2};" : "=l"(d) : "f"(lo), "f"(hi))
#define UPK(lo, hi, s) asm("mov.b64 {%0, %1}, %2;" : "=f"(lo), "=f"(hi) : "l"(s))
#define FMA2(d, a, b, c) \
    asm("fma.rn.f32x2 %0, %1, %2, %3;" : "=l"(d) : "l"(a), "l"(b), "l"(c))
#define MUL2(d, a, b) \
    asm("mul.rn.f32x2 %0, %1, %2;" : "=l"(d) : "l"(a), "l"(b))

__device__ __forceinline__ float tanh_hw(float x) {
    float r;
    asm("tanh.approx.f32 %0, %1;" : "=f"(r) : "f"(x));
    return r;
}

// swizzle: logical pair index jp (0..31) -> stored u64 index.
// s = jp>>3 (slice), q = jp&7, c = q>>1 (16B chunk), t = q&1.
// stored index = (c*4 + s)*2 + t  -> lane s, chunk c reads 16B at (c*4+s)*16.
__device__ __forceinline__ int swz_pair(int jp) {
    int s = jp >> 3, q = jp & 7, c = q >> 1, t = q & 1;
    return ((c * 4 + s) << 1) | t;
}

__global__ void __launch_bounds__(512, 1)
backward_rpm_kernel(const float* __restrict__ spectrum,  // (16384, 40)
                    const float* __restrict__ W1,        // (6, 64)
                    const float* __restrict__ b1,        // (64,)
                    const float* __restrict__ W2,        // (64, 40)
                    const float* __restrict__ b2,        // (40,)
                    const float* __restrict__ R,         // (8, 40)
                    float* __restrict__ out)             // (16384, 6)
{
    __shared__ float sA [PROJ * HID];       // scratch: A = R W2^T
    __shared__ u64   sW1p[NU * HID2];       // W1 pairs, swizzled chunks
    __shared__ u64   sB1p[HID2];            // b1 pairs, swizzled chunks
    __shared__ u64   sMp [NU * HID2];       // M pairs, swizzled chunks
    __shared__ float sP  [NU * NSPEC];      // P = R6^T R
    __shared__ float sB2 [NSPEC];

    const int tid = threadIdx.x;

    // ---- one-time weight prep ----
    {
        // W1 / b1 with swizzled pair layout
        float* fW1 = (float*)sW1p;
        for (int i = tid; i < NU * HID; i += 512) {
            int k = i >> 6, j = i & 63;
            int jp = j >> 1, half = j & 1;
            fW1[k * HID + swz_pair(jp) * 2 + half] = W1[i];
        }
        if (tid < HID) {
            int jp = tid >> 1, half = tid & 1;
            ((float*)sB1p)[swz_pair(jp) * 2 + half] = b1[tid];
        }
        if (tid < NSPEC) sB2[tid] = b2[tid];

        // A[p][j] = sum_k R[p][k] * W2[j][k]  (512 entries, one per thread)
        {
            int p = tid >> 6, j = tid & 63;
            float acc = 0.0f;
            #pragma unroll
            for (int k = 0; k < NSPEC; k++)
                acc = fmaf(R[p * NSPEC + k], W2[j * NSPEC + k], acc);
            sA[tid] = acc;
        }
        __syncthreads();

        // M[i][j] = sum_p R[p][i] * A[p][j]  (384 entries, swizzled store)
        float* fM = (float*)sMp;
        for (int idx = tid; idx < NU * HID; idx += 512) {
            int i = idx >> 6, j = idx & 63;
            float acc = 0.0f;
            #pragma unroll
            for (int p = 0; p < PROJ; p++)
                acc = fmaf(R[p * NSPEC + i], sA[p * HID + j], acc);
            int jp = j >> 1, half = j & 1;
            fM[i * HID + swz_pair(jp) * 2 + half] = acc;
        }
        // P[i][k] = sum_p R[p][i] * R[p][k]  (240 entries)
        for (int idx = tid; idx < NU * NSPEC; idx += 512) {
            int i = idx / NSPEC, k = idx % NSPEC;
            float acc = 0.0f;
            #pragma unroll
            for (int p = 0; p < PROJ; p++)
                acc = fmaf(R[p * NSPEC + i], R[p * NSPEC + k], acc);
            sP[idx] = acc;
        }
        __syncthreads();
    }

    // ---- per-element setup: 4 threads/element, contiguous 8-pair slices ----
    const int s    = tid & 3;                 // slice: logical pairs s*8..s*8+7
    const int elem = blockIdx.x * 128 + (tid >> 2);
    const float* sp = spectrum + elem * NSPEC;

    // cl2[i]: packed (P (b2-spec))[i] on lane s==0 only (folded into gp init);
    // final update multiplies the whole reduced sum by -LR.
    u64 cl2[NU];
    #pragma unroll
    for (int i = 0; i < NU; i++) {
        float acc = 0.0f;
        #pragma unroll
        for (int k = 0; k < NSPEC; k++)
            acc = fmaf(sP[i * NSPEC + k], sB2[k] - sp[k], acc);
        float v = (s == 0) ? acc : 0.0f;
        PK(cl2[i], v, 0.0f);
    }

    float u[NU];
    #pragma unroll
    for (int k = 0; k < NU; k++) u[k] = 0.5f;

    // lane's chunk base (u64 units): chunk c at (c*4+s)*2
    const int cb = s * 2;

    #pragma unroll 1
    for (int step = 0; step < STEPS; step++) {
        // duplicated-packed u
        u64 ud[NU];
        #pragma unroll
        for (int k = 0; k < NU; k++) PK(ud[k], u[k], u[k]);

        // ---- pre-activation: 4 conflict-free LDS.128 per row ----
        u64 pre[8];
        {
            const ulonglong2* bv = reinterpret_cast<const ulonglong2*>(sB1p);
            #pragma unroll
            for (int c = 0; c < 4; c++) {
                ulonglong2 t = bv[c * 4 + s];
                pre[c * 2]     = t.x;
                pre[c * 2 + 1] = t.y;
            }
        }
        #pragma unroll
        for (int k = 0; k < NU; k++) {
            const ulonglong2* wv =
                reinterpret_cast<const ulonglong2*>(&sW1p[k * HID2]);
            #pragma unroll
            for (int c = 0; c < 4; c++) {
                ulonglong2 w = wv[c * 4 + s];
                FMA2(pre[c * 2],     ud[k], w.x, pre[c * 2]);
                FMA2(pre[c * 2 + 1], ud[k], w.y, pre[c * 2 + 1]);
            }
        }

        // ---- h = tanh(pre) via MUFU.TANH ----
        #pragma unroll
        for (int jj = 0; jj < 8; jj++) {
            float a, b;
            UPK(a, b, pre[jj]);
            a = tanh_hw(a);
            b = tanh_hw(b);
            PK(pre[jj], a, b);
        }

        // ---- grad partials (cl2 folded into init FMA) ----
        u64 gp[NU];
        #pragma unroll
        for (int i = 0; i < NU; i++) {
            const ulonglong2* mv =
                reinterpret_cast<const ulonglong2*>(&sMp[i * HID2]);
            ulonglong2 m0 = mv[0 * 4 + s];
            FMA2(gp[i], m0.x, pre[0], cl2[i]);
            FMA2(gp[i], m0.y, pre[1], gp[i]);
            #pragma unroll
            for (int c = 1; c < 4; c++) {
                ulonglong2 m = mv[c * 4 + s];
                FMA2(gp[i], m.x, pre[c * 2],     gp[i]);
                FMA2(gp[i], m.y, pre[c * 2 + 1], gp[i]);
            }
        }

        // ---- horizontal + 4-lane butterfly reduce ----
        float g[NU];
        #pragma unroll
        for (int i = 0; i < NU; i++) {
            float a, b;
            UPK(a, b, gp[i]);
            g[i] = a + b;
        }
        #pragma unroll
        for (int i = 0; i < NU; i++)
            g[i] += __shfl_xor_sync(0xFFFFFFFFu, g[i], 1);
        #pragma unroll
        for (int i = 0; i < NU; i++)
            g[i] += __shfl_xor_sync(0xFFFFFFFFu, g[i], 2);

        // ---- update + clamp (all 4 lanes identical) ----
        #pragma unroll
        for (int i = 0; i < NU; i++) {
            float t = fmaf(-LRATE, g[i], u[i]);
            u[i] = fminf(fmaxf(t, 0.0f), 1.0f);
        }
    }

    if (s == 0) {
        #pragma unroll
        for (int k = 0; k < NU; k++)
            out[elem * NU + k] = u[k];
    }
}

extern "C" void kernel_launch(void* const* d_in, const int* in_sizes, int n_in,
                              void* d_out, int out_size) {
    const float* spectrum = (const float*)d_in[0];
    const float* W1 = (const float*)d_in[1];
    const float* b1 = (const float*)d_in[2];
    const float* W2 = (const float*)d_in[3];
    const float* b2 = (const float*)d_in[4];
    const float* R  = (const float*)d_in[5];
    float* out = (float*)d_out;

    backward_rpm_kernel<<<BATCH / 128, 512>>>(spectrum, W1, b1, W2, b2, R, out);
}